// round 14
// baseline (speedup 1.0000x reference)
#include <cuda_runtime.h>
#include <cuda_fp16.h>
#include <cstdint>

// Problem constants
#define B_     4
#define NQ     2048
#define DQ     1024
#define NK     1024
#define DC     768
#define HEADS  16
#define DH     64
#define INNER  1024   // HEADS*DH

// ---------------------------------------------------------------------------
// Device scratch (static globals). Single fp16 everywhere. Weights natural [K,N].
// ---------------------------------------------------------------------------
__device__ __half g_x [(size_t)B_ * NQ * DQ];
__device__ __half g_c [(size_t)B_ * NK * DC];
__device__ __half g_q [(size_t)B_ * NQ * INNER];
__device__ __half g_k [(size_t)B_ * NK * INNER];
__device__ __half g_v [(size_t)B_ * NK * INNER];
__device__ __half g_ao[(size_t)B_ * NQ * INNER];
__device__ __half g_wq[(size_t)DQ * INNER];
__device__ __half g_wk[(size_t)DC * INNER];
__device__ __half g_wv[(size_t)DC * INNER];
__device__ __half g_wo[(size_t)INNER * DQ];

// ---------------------------------------------------------------------------
// PTX helpers (sm_80-era only: cp.async, ldmatrix, mma.sync)
// ---------------------------------------------------------------------------
__device__ __forceinline__ uint32_t smem_u32(const void* p) {
    uint32_t a;
    asm("{ .reg .u64 t; cvta.to.shared.u64 t, %1; cvt.u32.u64 %0, t; }"
        : "=r"(a) : "l"(p));
    return a;
}
__device__ __forceinline__ void cp_async16(uint32_t s, const void* g) {
    asm volatile("cp.async.cg.shared.global [%0], [%1], 16;" :: "r"(s), "l"(g));
}
__device__ __forceinline__ void ldsm_x4(uint32_t* r, uint32_t a) {
    asm volatile("ldmatrix.sync.aligned.m8n8.x4.shared.b16 {%0,%1,%2,%3}, [%4];"
                 : "=r"(r[0]), "=r"(r[1]), "=r"(r[2]), "=r"(r[3]) : "r"(a));
}
__device__ __forceinline__ void ldsm_x4_t(uint32_t* r, uint32_t a) {
    asm volatile("ldmatrix.sync.aligned.m8n8.x4.trans.shared.b16 {%0,%1,%2,%3}, [%4];"
                 : "=r"(r[0]), "=r"(r[1]), "=r"(r[2]), "=r"(r[3]) : "r"(a));
}
__device__ __forceinline__ void mma_f16(float* d, const uint32_t a[4],
                                        uint32_t b0, uint32_t b1) {
    asm volatile(
        "mma.sync.aligned.m16n8k16.row.col.f32.f16.f16.f32 "
        "{%0,%1,%2,%3}, {%4,%5,%6,%7}, {%8,%9}, {%0,%1,%2,%3};"
        : "+f"(d[0]), "+f"(d[1]), "+f"(d[2]), "+f"(d[3])
        : "r"(a[0]), "r"(a[1]), "r"(a[2]), "r"(a[3]), "r"(b0), "r"(b1));
}
#define SW64(o)  ((o) ^ (((o) >> 3) & 0x30))
#define SW128(o) ((o) ^ (((o) >> 3) & 0x70))
#define CP_COMMIT() asm volatile("cp.async.commit_group;" ::: "memory")
#define CP_WAIT0()  asm volatile("cp.async.wait_group 0;" ::: "memory")
#define CP_WAIT1()  asm volatile("cp.async.wait_group 1;" ::: "memory")

__device__ __forceinline__ uint32_t pack_h(float a, float b) {
    __half2 t = __floats2half2_rn(a, b);
    return *(uint32_t*)&t;
}

// ---------------------------------------------------------------------------
// fp16 GEMM (round-10 exact config — best measured): C = A[M,K] @ W[K,N].
// CTA 128x128x32, 512 thr (16 warps 4x4), warp 32x32, 3-stage ring, 48 KB,
// 2 CTAs/SM. MODE 0: fused QKV (z selects A/W/C); MODE 1: f32 + bias out.
// ---------------------------------------------------------------------------
#define GSTAGE_B  16384                // A(8K) B(8K)
#define GEMM_SMEM (3 * GSTAGE_B)       // 48 KB

template <int MODE>
__global__ __launch_bounds__(512, 2)
void mma_gemm(const __half* __restrict__ Ax, const __half* __restrict__ Ac,
              const __half* __restrict__ W0, const __half* __restrict__ W1,
              const __half* __restrict__ W2,
              __half* __restrict__ C0, __half* __restrict__ C1,
              __half* __restrict__ C2,
              const float* __restrict__ bias, float* __restrict__ Cf)
{
    const int z = blockIdx.z;
    const bool active = !(MODE == 0 && z > 0 && blockIdx.y >= (B_ * NK) / 128);
    if (!active) return;   // uniform per-CTA: all threads exit before any sync

    extern __shared__ __align__(1024) char smraw[];
    const uint32_t sb = smem_u32(smraw);
    const int tid  = threadIdx.x;
    const int wid  = tid >> 5, lane = tid & 31;
    const int wm   = wid & 3,  wn   = wid >> 2;     // 4 x 4 warp grid
    const int row0 = blockIdx.y * 128, col0 = blockIdx.x * 128;
    const int lsel = lane & 15;
    const int khf  = (lane >> 4) * 16;
    const int tt   = lane >> 3;

    const __half* A;
    const __half* W;
    __half* Ch;
    int K;
    if (MODE == 1) {
        A = Ax; W = W0; Ch = nullptr; K = INNER;
    } else if (z == 0) {
        A = Ax; W = W0; Ch = C0; K = DQ;
    } else if (z == 1) {
        A = Ac; W = W1; Ch = C1; K = DC;
    } else {
        A = Ac; W = W2; Ch = C2; K = DC;
    }
    const int N = 1024;
    const int nch = K >> 5;

    float acc[2][4][4];
#pragma unroll
    for (int i = 0; i < 2; i++)
#pragma unroll
        for (int j = 0; j < 4; j++)
#pragma unroll
            for (int q = 0; q < 4; q++) acc[i][j][q] = 0.f;

    const __half* aT = A + (size_t)row0 * K;

#define GISSUE(c)                                                              \
    do {                                                                       \
        const uint32_t stg_ = sb + ((c) % 3) * GSTAGE_B;                       \
        const int k0_ = (c) << 5;                                              \
        /* A: 128 rows x 64B (512 f4) */                                       \
        {                                                                      \
            const int cc = tid;                                                \
            const int r = cc >> 2, cl = cc & 3;                                \
            const uint32_t off = r * 64 + cl * 16;                             \
            cp_async16(stg_ + SW64(off), aT + (size_t)r * K + k0_ + cl * 8);   \
        }                                                                      \
        /* B: 32 rows x 256B, two 64-col halves (512 f4) */                    \
        {                                                                      \
            const int cc = tid;                                                \
            const int half = cc >> 8;                                          \
            const int c2 = cc & 255;                                           \
            const int r = c2 >> 3, seg = c2 & 7;                               \
            const uint32_t off = r * 128 + seg * 16;                           \
            cp_async16(stg_ + 8192 + half * 4096 + SW128(off),                 \
                       W + (size_t)(k0_ + r) * N + col0 + half * 64 + seg * 8);\
        }                                                                      \
        CP_COMMIT();                                                           \
    } while (0)

    GISSUE(0);
    GISSUE(1);
    for (int c = 0; c < nch; c++) {
        if (c + 1 < nch) { CP_WAIT1(); } else { CP_WAIT0(); }
        __syncthreads();
        if (c + 2 < nch) GISSUE(c + 2);

        const uint32_t stg = sb + (c % 3) * GSTAGE_B;
#pragma unroll
        for (int ks = 0; ks < 2; ks++) {
            uint32_t af[2][4], bf[2][4];
#pragma unroll
            for (int mt = 0; mt < 2; mt++) {
                const uint32_t off = (wm * 32 + mt * 16 + lsel) * 64 + ks * 32 + khf;
                ldsm_x4(af[mt], stg + SW64(off));
            }
#pragma unroll
            for (int gg = 0; gg < 2; gg++) {
                const int g = (wn & 1) * 2 + gg;
                const uint32_t off = (ks * 16 + (lane & 7) + ((tt >> 1) << 3)) * 128
                                     + g * 32 + (tt & 1) * 16;
                const uint32_t sw = SW128(off) + (wn >> 1) * 4096;
                ldsm_x4_t(bf[gg], stg + 8192 + sw);
            }
#pragma unroll
            for (int gg = 0; gg < 2; gg++)
#pragma unroll
                for (int mt = 0; mt < 2; mt++)
#pragma unroll
                    for (int nt = 0; nt < 2; nt++)
                        mma_f16(acc[mt][gg * 2 + nt], af[mt], bf[gg][nt], bf[gg][2 + nt]);
        }
    }
#undef GISSUE

    const int rb = row0 + wm * 32 + (lane >> 2);
    const int cb = col0 + wn * 32 + (lane & 3) * 2;
#pragma unroll
    for (int mt = 0; mt < 2; mt++) {
#pragma unroll
        for (int j = 0; j < 4; j++) {
            const int col = cb + j * 8;
            const int r0 = rb + mt * 16;
            float d0 = acc[mt][j][0], d1 = acc[mt][j][1];
            float d2 = acc[mt][j][2], d3 = acc[mt][j][3];
            if (MODE == 1) {
                float b0 = bias[col], b1 = bias[col + 1];
                *(float2*)(Cf + (size_t)r0 * N + col)       = make_float2(d0 + b0, d1 + b1);
                *(float2*)(Cf + (size_t)(r0 + 8) * N + col) = make_float2(d2 + b0, d3 + b1);
            } else {
                *(uint32_t*)(Ch + (size_t)r0 * N + col)       = pack_h(d0, d1);
                *(uint32_t*)(Ch + (size_t)(r0 + 8) * N + col) = pack_h(d2, d3);
            }
        }
    }
}

// ---------------------------------------------------------------------------
// Flash attention via fp16 mma.sync single-pass.
// CTA: 128 q-rows x head x batch; 8 warps x 16 rows.
// NOW: 3-stage KV ring (64 KB), wait_group 1 overlap, 2 CTAs/SM.
// ---------------------------------------------------------------------------
#define AQ_OFF   0
#define AR_BASE  16384
#define AR_STAGE 16384
#define AV_OFF   8192
#define ATTN_SMEM (16384 + 3 * 16384)   // 64 KB

__global__ __launch_bounds__(256, 2)
void attn_mma(const __half* __restrict__ qg, const __half* __restrict__ kg,
              const __half* __restrict__ vg, __half* __restrict__ aog)
{
    extern __shared__ __align__(1024) char smraw[];
    const uint32_t sb = smem_u32(smraw);
    const int tid = threadIdx.x, lane = tid & 31, w = tid >> 5;
    const int q0 = blockIdx.x * 128;
    const int h  = blockIdx.y;
    const int b  = blockIdx.z;
    const int lsel = lane & 15;
    const int khf  = (lane >> 4) * 16;
    const float SCALE = 0.125f;

    // Load Q tile [128 x 64] fp16 into smem (row 128B, SW128)
    const size_t qgb = ((size_t)b * NQ + q0) * INNER + h * DH;
#pragma unroll
    for (int j = 0; j < 4; j++) {
        int idx = tid + 256 * j;           // 0..1023
        int r = idx >> 3, seg = idx & 7;
        uint32_t off = r * 128 + seg * 16;
        *(float4*)(smraw + AQ_OFF + SW128(off)) =
            *(const float4*)(qg + qgb + (size_t)r * INNER + seg * 8);
    }

    float oacc[8][4];
#pragma unroll
    for (int j = 0; j < 8; j++)
#pragma unroll
        for (int q = 0; q < 4; q++) oacc[j][q] = 0.f;
    float m0 = -1e30f, m1 = -1e30f, l0 = 0.f, l1 = 0.f;

#define AT_ISSUE(kt)                                                           \
    do {                                                                       \
        const uint32_t stg_ = sb + AR_BASE + ((kt) % 3) * AR_STAGE;            \
        const size_t kvg = ((size_t)b * NK + (kt) * 64) * INNER + h * DH;      \
        _Pragma("unroll")                                                      \
        for (int j = 0; j < 4; j++) {                                          \
            int idx = tid + 256 * j;       /* 0..1023 */                       \
            int buf = idx >> 9;            /* 0:K 1:V */                       \
            int cc  = idx & 511;                                               \
            int r = cc >> 3, seg = cc & 7;                                     \
            uint32_t off = r * 128 + seg * 16;                                 \
            const __half* src = (buf ? vg : kg) + kvg + (size_t)r * INNER + seg * 8; \
            cp_async16(stg_ + buf * 8192 + SW128(off), src);                   \
        }                                                                      \
        CP_COMMIT();                                                           \
    } while (0)

    const int NT = NK / 64;
    AT_ISSUE(0);
    AT_ISSUE(1);
    for (int kt = 0; kt < NT; kt++) {
        if (kt + 1 < NT) { CP_WAIT1(); } else { CP_WAIT0(); }
        __syncthreads();                 // tile kt visible; compute of kt-1 done
        if (kt + 2 < NT) AT_ISSUE(kt + 2);
        const uint32_t stg = sb + AR_BASE + (kt % 3) * AR_STAGE;

        // ---- S = Q @ K^T ----
        float sacc[8][4];
#pragma unroll
        for (int j = 0; j < 8; j++)
#pragma unroll
            for (int q = 0; q < 4; q++) sacc[j][q] = 0.f;

#pragma unroll
        for (int ks = 0; ks < 4; ks++) {
            uint32_t qf[4];
            {
                uint32_t off = (w * 16 + lsel) * 128 + ks * 32 + khf;
                ldsm_x4(qf, sb + AQ_OFF + SW128(off));
            }
#pragma unroll
            for (int g = 0; g < 4; g++) {
                uint32_t kf[4];
                uint32_t off = (g * 16 + lsel) * 128 + ks * 32 + khf;
                ldsm_x4(kf, stg + SW128(off));
#pragma unroll
                for (int nt = 0; nt < 2; nt++)
                    mma_f16(sacc[g * 2 + nt], qf, kf[nt], kf[2 + nt]);
            }
        }

        // ---- online softmax ----
        float rx0 = -1e30f, rx1 = -1e30f;
#pragma unroll
        for (int j = 0; j < 8; j++) {
            rx0 = fmaxf(rx0, fmaxf(sacc[j][0], sacc[j][1]));
            rx1 = fmaxf(rx1, fmaxf(sacc[j][2], sacc[j][3]));
        }
#pragma unroll
        for (int off = 1; off <= 2; off <<= 1) {
            rx0 = fmaxf(rx0, __shfl_xor_sync(0xffffffffu, rx0, off));
            rx1 = fmaxf(rx1, __shfl_xor_sync(0xffffffffu, rx1, off));
        }
        float nm0 = fmaxf(m0, rx0 * SCALE), nm1 = fmaxf(m1, rx1 * SCALE);
        float c0 = __expf(m0 - nm0), c1 = __expf(m1 - nm1);
        m0 = nm0; m1 = nm1;

        float ps0 = 0.f, ps1 = 0.f;
        uint32_t pa[4][4];
#pragma unroll
        for (int t = 0; t < 4; t++) {
#pragma unroll
            for (int jj = 0; jj < 2; jj++) {
                int j = 2 * t + jj;
                float p00 = __expf(fmaf(sacc[j][0], SCALE, -nm0));
                float p01 = __expf(fmaf(sacc[j][1], SCALE, -nm0));
                float p10 = __expf(fmaf(sacc[j][2], SCALE, -nm1));
                float p11 = __expf(fmaf(sacc[j][3], SCALE, -nm1));
                ps0 += p00 + p01;
                ps1 += p10 + p11;
                pa[t][jj * 2]     = pack_h(p00, p01);
                pa[t][jj * 2 + 1] = pack_h(p10, p11);
            }
        }
#pragma unroll
        for (int off = 1; off <= 2; off <<= 1) {
            ps0 += __shfl_xor_sync(0xffffffffu, ps0, off);
            ps1 += __shfl_xor_sync(0xffffffffu, ps1, off);
        }
        l0 = l0 * c0 + ps0;
        l1 = l1 * c1 + ps1;
#pragma unroll
        for (int j = 0; j < 8; j++) {
            oacc[j][0] *= c0; oacc[j][1] *= c0;
            oacc[j][2] *= c1; oacc[j][3] *= c1;
        }

        // ---- O += P @ V ----
        const int tt = lane >> 3;
#pragma unroll
        for (int t = 0; t < 4; t++) {
#pragma unroll
            for (int g = 0; g < 4; g++) {
                uint32_t vf[4];
                uint32_t off = (t * 16 + (lane & 7) + (tt >> 1) * 8) * 128
                               + g * 32 + (tt & 1) * 16;
                ldsm_x4_t(vf, stg + AV_OFF + SW128(off));
#pragma unroll
                for (int nt = 0; nt < 2; nt++)
                    mma_f16(oacc[g * 2 + nt], pa[t], vf[nt], vf[2 + nt]);
            }
        }
    }
#undef AT_ISSUE

    const float inv0 = 1.f / l0, inv1 = 1.f / l1;
    const int r0g = q0 + w * 16 + (lane >> 2);
    const int r1g = r0g + 8;
    const int cbase = h * DH + (lane & 3) * 2;
#pragma unroll
    for (int j = 0; j < 8; j++) {
        const int col = cbase + j * 8;
        *(uint32_t*)(aog + ((size_t)b * NQ + r0g) * INNER + col) =
            pack_h(oacc[j][0] * inv0, oacc[j][1] * inv0);
        *(uint32_t*)(aog + ((size_t)b * NQ + r1g) * INNER + col) =
            pack_h(oacc[j][2] * inv1, oacc[j][3] * inv1);
    }
}

// ---------------------------------------------------------------------------
// fp32 -> fp16 converts, split in two launches (puts attn at ncu slot 3)
// ---------------------------------------------------------------------------
#define N4_X  (B_ * NQ * DQ / 4)
#define N4_C  (B_ * NK * DC / 4)
#define ACT_TOT (N4_X + N4_C)
#define N4_WQ (DQ * INNER / 4)
#define N4_WK (DC * INNER / 4)
#define N4_WV (DC * INNER / 4)
#define N4_WO (INNER * DQ / 4)
#define W1_ (N4_WQ)
#define W2_ (W1_ + N4_WK)
#define W3_ (W2_ + N4_WV)
#define W4_ (W3_ + N4_WO)

__global__ void cvt_act(const float4* __restrict__ x, const float4* __restrict__ ctx)
{
    int i = blockIdx.x * blockDim.x + threadIdx.x;
    if (i >= ACT_TOT) return;
    const float4* in;
    __half2* dst;
    int idx;
    if (i < N4_X) { in = x;   dst = (__half2*)g_x; idx = i; }
    else          { in = ctx; dst = (__half2*)g_c; idx = i - N4_X; }
    float4 v = in[idx];
    dst[2 * idx]     = __floats2half2_rn(v.x, v.y);
    dst[2 * idx + 1] = __floats2half2_rn(v.z, v.w);
}

__global__ void cvt_w(const float4* __restrict__ wq, const float4* __restrict__ wk,
                      const float4* __restrict__ wv, const float4* __restrict__ wo)
{
    int i = blockIdx.x * blockDim.x + threadIdx.x;
    if (i >= W4_) return;
    const float4* in;
    __half2* dst;
    int idx;
    if      (i < W1_) { in = wq; dst = (__half2*)g_wq; idx = i; }
    else if (i < W2_) { in = wk; dst = (__half2*)g_wk; idx = i - W1_; }
    else if (i < W3_) { in = wv; dst = (__half2*)g_wv; idx = i - W2_; }
    else              { in = wo; dst = (__half2*)g_wo; idx = i - W3_; }
    float4 v = in[idx];
    dst[2 * idx]     = __floats2half2_rn(v.x, v.y);
    dst[2 * idx + 1] = __floats2half2_rn(v.z, v.w);
}

// ---------------------------------------------------------------------------
// Launch: cvt_act(0), cvt_w(1), gemmQKV(2), attn(3) <- ncu slot, gemmO(4)
// ---------------------------------------------------------------------------
extern "C" void kernel_launch(void* const* d_in, const int* in_sizes, int n_in,
                              void* d_out, int out_size)
{
    const float* x   = (const float*)d_in[0];
    const float* ctx = (const float*)d_in[1];
    const float* Wq  = (const float*)d_in[2];
    const float* Wk  = (const float*)d_in[3];
    const float* Wv  = (const float*)d_in[4];
    const float* Wo  = (const float*)d_in[5];
    const float* bo  = (const float*)d_in[6];
    float* out = (float*)d_out;

    __half *xp, *cp, *qp, *kp, *vp, *aop, *wqp, *wkp, *wvp, *wop;
    cudaGetSymbolAddress((void**)&xp,  g_x);
    cudaGetSymbolAddress((void**)&cp,  g_c);
    cudaGetSymbolAddress((void**)&qp,  g_q);
    cudaGetSymbolAddress((void**)&kp,  g_k);
    cudaGetSymbolAddress((void**)&vp,  g_v);
    cudaGetSymbolAddress((void**)&aop, g_ao);
    cudaGetSymbolAddress((void**)&wqp, g_wq);
    cudaGetSymbolAddress((void**)&wkp, g_wk);
    cudaGetSymbolAddress((void**)&wvp, g_wv);
    cudaGetSymbolAddress((void**)&wop, g_wo);

    cudaFuncSetAttribute(mma_gemm<0>, cudaFuncAttributeMaxDynamicSharedMemorySize, GEMM_SMEM);
    cudaFuncSetAttribute(mma_gemm<1>, cudaFuncAttributeMaxDynamicSharedMemorySize, GEMM_SMEM);
    cudaFuncSetAttribute(attn_mma, cudaFuncAttributeMaxDynamicSharedMemorySize, ATTN_SMEM);

    // 0: convert activations
    cvt_act<<<(ACT_TOT + 255) / 256, 256>>>((const float4*)x, (const float4*)ctx);
    // 1: convert weights
    cvt_w<<<(W4_ + 255) / 256, 256>>>((const float4*)Wq, (const float4*)Wk,
                                      (const float4*)Wv, (const float4*)Wo);

    // 2: fused Q+K+V projections (z: 0=Q over x, 1=K, 2=V over ctx)
    mma_gemm<0><<<dim3(INNER / 128, (B_ * NQ) / 128, 3), 512, GEMM_SMEM>>>(
        xp, cp, wqp, wkp, wvp, qp, kp, vp, nullptr, nullptr);

    // 3: attention (ncu capture slot)
    attn_mma<<<dim3(NQ / 128, HEADS, B_), 256, ATTN_SMEM>>>(qp, kp, vp, aop);

    // 4: output projection -> fp32 + bias
    mma_gemm<1><<<dim3(DQ / 128, (B_ * NQ) / 128, 1), 512, GEMM_SMEM>>>(
        aop, nullptr, wop, nullptr, nullptr, nullptr, nullptr, nullptr,
        bo, out);
}

// round 15
// speedup vs baseline: 1.5195x; 1.5195x over previous
#include <cuda_runtime.h>
#include <cuda_fp16.h>
#include <cstdint>

// Problem constants
#define B_     4
#define NQ     2048
#define DQ     1024
#define NK     1024
#define DC     768
#define HEADS  16
#define DH     64
#define INNER  1024   // HEADS*DH

// ---------------------------------------------------------------------------
// Device scratch (static globals). Single fp16 everywhere. Weights natural [K,N].
// ---------------------------------------------------------------------------
__device__ __half g_x [(size_t)B_ * NQ * DQ];
__device__ __half g_c [(size_t)B_ * NK * DC];
__device__ __half g_q [(size_t)B_ * NQ * INNER];
__device__ __half g_k [(size_t)B_ * NK * INNER];
__device__ __half g_v [(size_t)B_ * NK * INNER];
__device__ __half g_ao[(size_t)B_ * NQ * INNER];
__device__ __half g_wq[(size_t)DQ * INNER];
__device__ __half g_wk[(size_t)DC * INNER];
__device__ __half g_wv[(size_t)DC * INNER];
__device__ __half g_wo[(size_t)INNER * DQ];

// ---------------------------------------------------------------------------
// PTX helpers (sm_80-era only: cp.async, ldmatrix, mma.sync)
// ---------------------------------------------------------------------------
__device__ __forceinline__ uint32_t smem_u32(const void* p) {
    uint32_t a;
    asm("{ .reg .u64 t; cvta.to.shared.u64 t, %1; cvt.u32.u64 %0, t; }"
        : "=r"(a) : "l"(p));
    return a;
}
__device__ __forceinline__ void cp_async16(uint32_t s, const void* g) {
    asm volatile("cp.async.cg.shared.global [%0], [%1], 16;" :: "r"(s), "l"(g));
}
__device__ __forceinline__ void ldsm_x4(uint32_t* r, uint32_t a) {
    asm volatile("ldmatrix.sync.aligned.m8n8.x4.shared.b16 {%0,%1,%2,%3}, [%4];"
                 : "=r"(r[0]), "=r"(r[1]), "=r"(r[2]), "=r"(r[3]) : "r"(a));
}
__device__ __forceinline__ void ldsm_x4_t(uint32_t* r, uint32_t a) {
    asm volatile("ldmatrix.sync.aligned.m8n8.x4.trans.shared.b16 {%0,%1,%2,%3}, [%4];"
                 : "=r"(r[0]), "=r"(r[1]), "=r"(r[2]), "=r"(r[3]) : "r"(a));
}
__device__ __forceinline__ void mma_f16(float* d, const uint32_t a[4],
                                        uint32_t b0, uint32_t b1) {
    asm volatile(
        "mma.sync.aligned.m16n8k16.row.col.f32.f16.f16.f32 "
        "{%0,%1,%2,%3}, {%4,%5,%6,%7}, {%8,%9}, {%0,%1,%2,%3};"
        : "+f"(d[0]), "+f"(d[1]), "+f"(d[2]), "+f"(d[3])
        : "r"(a[0]), "r"(a[1]), "r"(a[2]), "r"(a[3]), "r"(b0), "r"(b1));
}
#define SW64(o)  ((o) ^ (((o) >> 3) & 0x30))
#define SW128(o) ((o) ^ (((o) >> 3) & 0x70))
#define CP_COMMIT() asm volatile("cp.async.commit_group;" ::: "memory")
#define CP_WAIT0()  asm volatile("cp.async.wait_group 0;" ::: "memory")
#define CP_WAIT1()  asm volatile("cp.async.wait_group 1;" ::: "memory")

__device__ __forceinline__ uint32_t pack_h(float a, float b) {
    __half2 t = __floats2half2_rn(a, b);
    return *(uint32_t*)&t;
}

// ---------------------------------------------------------------------------
// fp16 GEMM (round-10 exact mainloop — best measured): C = A[M,K] @ W[K,N].
// CTA 128x128x32, 512 thr (16 warps 4x4), warp 32x32, 3-stage ring, 48 KB,
// 2 CTAs/SM. MODE 0: fused QKV, z folded into blockIdx.y (compact grid);
// MODE 1: f32 + bias out.
// ---------------------------------------------------------------------------
#define GSTAGE_B  16384                // A(8K) B(8K)
#define GEMM_SMEM (3 * GSTAGE_B)       // 48 KB

template <int MODE>
__global__ __launch_bounds__(512, 2)
void mma_gemm(const __half* __restrict__ Ax, const __half* __restrict__ Ac,
              const __half* __restrict__ W0, const __half* __restrict__ W1,
              const __half* __restrict__ W2,
              __half* __restrict__ C0, __half* __restrict__ C1,
              __half* __restrict__ C2,
              const float* __restrict__ bias, float* __restrict__ Cf)
{
    extern __shared__ __align__(1024) char smraw[];
    const uint32_t sb = smem_u32(smraw);
    const int tid  = threadIdx.x;
    const int wid  = tid >> 5, lane = tid & 31;
    const int wm   = wid & 3,  wn   = wid >> 2;     // 4 x 4 warp grid
    const int lsel = lane & 15;
    const int khf  = (lane >> 4) * 16;
    const int tt   = lane >> 3;

    // Decode tile set (MODE 0: y in [0,64)=Q, [64,96)=K, [96,128)=V)
    const __half* A;
    const __half* W;
    __half* Ch;
    int K, yt;
    if (MODE == 1) {
        A = Ax; W = W0; Ch = nullptr; K = INNER; yt = blockIdx.y;
    } else {
        const int yb = blockIdx.y;
        if (yb < 64)      { A = Ax; W = W0; Ch = C0; K = DQ; yt = yb; }
        else if (yb < 96) { A = Ac; W = W1; Ch = C1; K = DC; yt = yb - 64; }
        else              { A = Ac; W = W2; Ch = C2; K = DC; yt = yb - 96; }
    }
    const int row0 = yt * 128, col0 = blockIdx.x * 128;
    const int N = 1024;
    const int nch = K >> 5;

    float acc[2][4][4];
#pragma unroll
    for (int i = 0; i < 2; i++)
#pragma unroll
        for (int j = 0; j < 4; j++)
#pragma unroll
            for (int q = 0; q < 4; q++) acc[i][j][q] = 0.f;

    const __half* aT = A + (size_t)row0 * K;

#define GISSUE(c)                                                              \
    do {                                                                       \
        const uint32_t stg_ = sb + ((c) % 3) * GSTAGE_B;                       \
        const int k0_ = (c) << 5;                                              \
        /* A: 128 rows x 64B (512 f4) */                                       \
        {                                                                      \
            const int cc = tid;                                                \
            const int r = cc >> 2, cl = cc & 3;                                \
            const uint32_t off = r * 64 + cl * 16;                             \
            cp_async16(stg_ + SW64(off), aT + (size_t)r * K + k0_ + cl * 8);   \
        }                                                                      \
        /* B: 32 rows x 256B, two 64-col halves (512 f4) */                    \
        {                                                                      \
            const int cc = tid;                                                \
            const int half = cc >> 8;                                          \
            const int c2 = cc & 255;                                           \
            const int r = c2 >> 3, seg = c2 & 7;                               \
            const uint32_t off = r * 128 + seg * 16;                           \
            cp_async16(stg_ + 8192 + half * 4096 + SW128(off),                 \
                       W + (size_t)(k0_ + r) * N + col0 + half * 64 + seg * 8);\
        }                                                                      \
        CP_COMMIT();                                                           \
    } while (0)

    GISSUE(0);
    GISSUE(1);
    for (int c = 0; c < nch; c++) {
        if (c + 1 < nch) { CP_WAIT1(); } else { CP_WAIT0(); }
        __syncthreads();
        if (c + 2 < nch) GISSUE(c + 2);

        const uint32_t stg = sb + (c % 3) * GSTAGE_B;
#pragma unroll
        for (int ks = 0; ks < 2; ks++) {
            uint32_t af[2][4], bf[2][4];
#pragma unroll
            for (int mt = 0; mt < 2; mt++) {
                const uint32_t off = (wm * 32 + mt * 16 + lsel) * 64 + ks * 32 + khf;
                ldsm_x4(af[mt], stg + SW64(off));
            }
#pragma unroll
            for (int gg = 0; gg < 2; gg++) {
                const int g = (wn & 1) * 2 + gg;
                const uint32_t off = (ks * 16 + (lane & 7) + ((tt >> 1) << 3)) * 128
                                     + g * 32 + (tt & 1) * 16;
                const uint32_t sw = SW128(off) + (wn >> 1) * 4096;
                ldsm_x4_t(bf[gg], stg + 8192 + sw);
            }
#pragma unroll
            for (int gg = 0; gg < 2; gg++)
#pragma unroll
                for (int mt = 0; mt < 2; mt++)
#pragma unroll
                    for (int nt = 0; nt < 2; nt++)
                        mma_f16(acc[mt][gg * 2 + nt], af[mt], bf[gg][nt], bf[gg][2 + nt]);
        }
    }
#undef GISSUE

    const int rb = row0 + wm * 32 + (lane >> 2);
    const int cb = col0 + wn * 32 + (lane & 3) * 2;
#pragma unroll
    for (int mt = 0; mt < 2; mt++) {
#pragma unroll
        for (int j = 0; j < 4; j++) {
            const int col = cb + j * 8;
            const int r0 = rb + mt * 16;
            float d0 = acc[mt][j][0], d1 = acc[mt][j][1];
            float d2 = acc[mt][j][2], d3 = acc[mt][j][3];
            if (MODE == 1) {
                float b0 = bias[col], b1 = bias[col + 1];
                *(float2*)(Cf + (size_t)r0 * N + col)       = make_float2(d0 + b0, d1 + b1);
                *(float2*)(Cf + (size_t)(r0 + 8) * N + col) = make_float2(d2 + b0, d3 + b1);
            } else {
                *(uint32_t*)(Ch + (size_t)r0 * N + col)       = pack_h(d0, d1);
                *(uint32_t*)(Ch + (size_t)(r0 + 8) * N + col) = pack_h(d2, d3);
            }
        }
    }
}

// ---------------------------------------------------------------------------
// Flash attention via fp16 mma.sync single-pass (round-10/12 exact: 2-stage
// KV ring, 48 KB, (kt & 1) indexing). CTA: 128 q-rows x head x batch.
// ---------------------------------------------------------------------------
#define AQ_OFF   0
#define AR_BASE  16384
#define AR_STAGE 16384
#define AV_OFF   8192
#define ATTN_SMEM (16384 + 2 * 16384)   // 48 KB

__global__ __launch_bounds__(256, 2)
void attn_mma(const __half* __restrict__ qg, const __half* __restrict__ kg,
              const __half* __restrict__ vg, __half* __restrict__ aog)
{
    extern __shared__ __align__(1024) char smraw[];
    const uint32_t sb = smem_u32(smraw);
    const int tid = threadIdx.x, lane = tid & 31, w = tid >> 5;
    const int q0 = blockIdx.x * 128;
    const int h  = blockIdx.y;
    const int b  = blockIdx.z;
    const int lsel = lane & 15;
    const int khf  = (lane >> 4) * 16;
    const float SCALE = 0.125f;

    // Load Q tile [128 x 64] fp16 into smem (row 128B, SW128)
    const size_t qgb = ((size_t)b * NQ + q0) * INNER + h * DH;
#pragma unroll
    for (int j = 0; j < 4; j++) {
        int idx = tid + 256 * j;           // 0..1023
        int r = idx >> 3, seg = idx & 7;
        uint32_t off = r * 128 + seg * 16;
        *(float4*)(smraw + AQ_OFF + SW128(off)) =
            *(const float4*)(qg + qgb + (size_t)r * INNER + seg * 8);
    }

    float oacc[8][4];
#pragma unroll
    for (int j = 0; j < 8; j++)
#pragma unroll
        for (int q = 0; q < 4; q++) oacc[j][q] = 0.f;
    float m0 = -1e30f, m1 = -1e30f, l0 = 0.f, l1 = 0.f;

#define AT_ISSUE(kt)                                                           \
    do {                                                                       \
        const uint32_t stg_ = sb + AR_BASE + ((kt) & 1) * AR_STAGE;            \
        const size_t kvg = ((size_t)b * NK + (kt) * 64) * INNER + h * DH;      \
        _Pragma("unroll")                                                      \
        for (int j = 0; j < 4; j++) {                                          \
            int idx = tid + 256 * j;       /* 0..1023 */                       \
            int buf = idx >> 9;            /* 0:K 1:V */                       \
            int cc  = idx & 511;                                               \
            int r = cc >> 3, seg = cc & 7;                                     \
            uint32_t off = r * 128 + seg * 16;                                 \
            const __half* src = (buf ? vg : kg) + kvg + (size_t)r * INNER + seg * 8; \
            cp_async16(stg_ + buf * 8192 + SW128(off), src);                   \
        }                                                                      \
        CP_COMMIT();                                                           \
    } while (0)

    const int NT = NK / 64;
    AT_ISSUE(0);
    for (int kt = 0; kt < NT; kt++) {
        CP_WAIT0();
        __syncthreads();                 // tile kt visible; prev compute done
        if (kt + 1 < NT) AT_ISSUE(kt + 1);
        const uint32_t stg = sb + AR_BASE + (kt & 1) * AR_STAGE;

        // ---- S = Q @ K^T ----
        float sacc[8][4];
#pragma unroll
        for (int j = 0; j < 8; j++)
#pragma unroll
            for (int q = 0; q < 4; q++) sacc[j][q] = 0.f;

#pragma unroll
        for (int ks = 0; ks < 4; ks++) {
            uint32_t qf[4];
            {
                uint32_t off = (w * 16 + lsel) * 128 + ks * 32 + khf;
                ldsm_x4(qf, sb + AQ_OFF + SW128(off));
            }
#pragma unroll
            for (int g = 0; g < 4; g++) {
                uint32_t kf[4];
                uint32_t off = (g * 16 + lsel) * 128 + ks * 32 + khf;
                ldsm_x4(kf, stg + SW128(off));
#pragma unroll
                for (int nt = 0; nt < 2; nt++)
                    mma_f16(sacc[g * 2 + nt], qf, kf[nt], kf[2 + nt]);
            }
        }

        // ---- online softmax ----
        float rx0 = -1e30f, rx1 = -1e30f;
#pragma unroll
        for (int j = 0; j < 8; j++) {
            rx0 = fmaxf(rx0, fmaxf(sacc[j][0], sacc[j][1]));
            rx1 = fmaxf(rx1, fmaxf(sacc[j][2], sacc[j][3]));
        }
#pragma unroll
        for (int off = 1; off <= 2; off <<= 1) {
            rx0 = fmaxf(rx0, __shfl_xor_sync(0xffffffffu, rx0, off));
            rx1 = fmaxf(rx1, __shfl_xor_sync(0xffffffffu, rx1, off));
        }
        float nm0 = fmaxf(m0, rx0 * SCALE), nm1 = fmaxf(m1, rx1 * SCALE);
        float c0 = __expf(m0 - nm0), c1 = __expf(m1 - nm1);
        m0 = nm0; m1 = nm1;

        float ps0 = 0.f, ps1 = 0.f;
        uint32_t pa[4][4];
#pragma unroll
        for (int t = 0; t < 4; t++) {
#pragma unroll
            for (int jj = 0; jj < 2; jj++) {
                int j = 2 * t + jj;
                float p00 = __expf(fmaf(sacc[j][0], SCALE, -nm0));
                float p01 = __expf(fmaf(sacc[j][1], SCALE, -nm0));
                float p10 = __expf(fmaf(sacc[j][2], SCALE, -nm1));
                float p11 = __expf(fmaf(sacc[j][3], SCALE, -nm1));
                ps0 += p00 + p01;
                ps1 += p10 + p11;
                pa[t][jj * 2]     = pack_h(p00, p01);
                pa[t][jj * 2 + 1] = pack_h(p10, p11);
            }
        }
#pragma unroll
        for (int off = 1; off <= 2; off <<= 1) {
            ps0 += __shfl_xor_sync(0xffffffffu, ps0, off);
            ps1 += __shfl_xor_sync(0xffffffffu, ps1, off);
        }
        l0 = l0 * c0 + ps0;
        l1 = l1 * c1 + ps1;
#pragma unroll
        for (int j = 0; j < 8; j++) {
            oacc[j][0] *= c0; oacc[j][1] *= c0;
            oacc[j][2] *= c1; oacc[j][3] *= c1;
        }

        // ---- O += P @ V ----
        const int tt = lane >> 3;
#pragma unroll
        for (int t = 0; t < 4; t++) {
#pragma unroll
            for (int g = 0; g < 4; g++) {
                uint32_t vf[4];
                uint32_t off = (t * 16 + (lane & 7) + (tt >> 1) * 8) * 128
                               + g * 32 + (tt & 1) * 16;
                ldsm_x4_t(vf, stg + AV_OFF + SW128(off));
#pragma unroll
                for (int nt = 0; nt < 2; nt++)
                    mma_f16(oacc[g * 2 + nt], pa[t], vf[nt], vf[2 + nt]);
            }
        }
    }
#undef AT_ISSUE

    const float inv0 = 1.f / l0, inv1 = 1.f / l1;
    const int r0g = q0 + w * 16 + (lane >> 2);
    const int r1g = r0g + 8;
    const int cbase = h * DH + (lane & 3) * 2;
#pragma unroll
    for (int j = 0; j < 8; j++) {
        const int col = cbase + j * 8;
        *(uint32_t*)(aog + ((size_t)b * NQ + r0g) * INNER + col) =
            pack_h(oacc[j][0] * inv0, oacc[j][1] * inv0);
        *(uint32_t*)(aog + ((size_t)b * NQ + r1g) * INNER + col) =
            pack_h(oacc[j][2] * inv1, oacc[j][3] * inv1);
    }
}

// ---------------------------------------------------------------------------
// fp32 -> fp16 converts, split in two launches (puts attn at ncu slot 3)
// ---------------------------------------------------------------------------
#define N4_X  (B_ * NQ * DQ / 4)
#define N4_C  (B_ * NK * DC / 4)
#define ACT_TOT (N4_X + N4_C)
#define N4_WQ (DQ * INNER / 4)
#define N4_WK (DC * INNER / 4)
#define N4_WV (DC * INNER / 4)
#define N4_WO (INNER * DQ / 4)
#define W1_ (N4_WQ)
#define W2_ (W1_ + N4_WK)
#define W3_ (W2_ + N4_WV)
#define W4_ (W3_ + N4_WO)

__global__ void cvt_act(const float4* __restrict__ x, const float4* __restrict__ ctx)
{
    int i = blockIdx.x * blockDim.x + threadIdx.x;
    if (i >= ACT_TOT) return;
    const float4* in;
    __half2* dst;
    int idx;
    if (i < N4_X) { in = x;   dst = (__half2*)g_x; idx = i; }
    else          { in = ctx; dst = (__half2*)g_c; idx = i - N4_X; }
    float4 v = in[idx];
    dst[2 * idx]     = __floats2half2_rn(v.x, v.y);
    dst[2 * idx + 1] = __floats2half2_rn(v.z, v.w);
}

__global__ void cvt_w(const float4* __restrict__ wq, const float4* __restrict__ wk,
                      const float4* __restrict__ wv, const float4* __restrict__ wo)
{
    int i = blockIdx.x * blockDim.x + threadIdx.x;
    if (i >= W4_) return;
    const float4* in;
    __half2* dst;
    int idx;
    if      (i < W1_) { in = wq; dst = (__half2*)g_wq; idx = i; }
    else if (i < W2_) { in = wk; dst = (__half2*)g_wk; idx = i - W1_; }
    else if (i < W3_) { in = wv; dst = (__half2*)g_wv; idx = i - W2_; }
    else              { in = wo; dst = (__half2*)g_wo; idx = i - W3_; }
    float4 v = in[idx];
    dst[2 * idx]     = __floats2half2_rn(v.x, v.y);
    dst[2 * idx + 1] = __floats2half2_rn(v.z, v.w);
}

// ---------------------------------------------------------------------------
// Launch: cvt_act(0), cvt_w(1), gemmQKV(2), attn(3) <- ncu slot, gemmO(4)
// ---------------------------------------------------------------------------
extern "C" void kernel_launch(void* const* d_in, const int* in_sizes, int n_in,
                              void* d_out, int out_size)
{
    const float* x   = (const float*)d_in[0];
    const float* ctx = (const float*)d_in[1];
    const float* Wq  = (const float*)d_in[2];
    const float* Wk  = (const float*)d_in[3];
    const float* Wv  = (const float*)d_in[4];
    const float* Wo  = (const float*)d_in[5];
    const float* bo  = (const float*)d_in[6];
    float* out = (float*)d_out;

    __half *xp, *cp, *qp, *kp, *vp, *aop, *wqp, *wkp, *wvp, *wop;
    cudaGetSymbolAddress((void**)&xp,  g_x);
    cudaGetSymbolAddress((void**)&cp,  g_c);
    cudaGetSymbolAddress((void**)&qp,  g_q);
    cudaGetSymbolAddress((void**)&kp,  g_k);
    cudaGetSymbolAddress((void**)&vp,  g_v);
    cudaGetSymbolAddress((void**)&aop, g_ao);
    cudaGetSymbolAddress((void**)&wqp, g_wq);
    cudaGetSymbolAddress((void**)&wkp, g_wk);
    cudaGetSymbolAddress((void**)&wvp, g_wv);
    cudaGetSymbolAddress((void**)&wop, g_wo);

    cudaFuncSetAttribute(mma_gemm<0>, cudaFuncAttributeMaxDynamicSharedMemorySize, GEMM_SMEM);
    cudaFuncSetAttribute(mma_gemm<1>, cudaFuncAttributeMaxDynamicSharedMemorySize, GEMM_SMEM);
    cudaFuncSetAttribute(attn_mma, cudaFuncAttributeMaxDynamicSharedMemorySize, ATTN_SMEM);

    // 0: convert activations
    cvt_act<<<(ACT_TOT + 255) / 256, 256>>>((const float4*)x, (const float4*)ctx);
    // 1: convert weights
    cvt_w<<<(W4_ + 255) / 256, 256>>>((const float4*)Wq, (const float4*)Wk,
                                      (const float4*)Wv, (const float4*)Wo);

    // 2: fused Q+K+V projections, compact grid (y: [0,64)=Q, [64,96)=K, [96,128)=V)
    mma_gemm<0><<<dim3(INNER / 128, 128, 1), 512, GEMM_SMEM>>>(
        xp, cp, wqp, wkp, wvp, qp, kp, vp, nullptr, nullptr);

    // 3: attention (ncu capture slot)
    attn_mma<<<dim3(NQ / 128, HEADS, B_), 256, ATTN_SMEM>>>(qp, kp, vp, aop);

    // 4: output projection -> fp32 + bias
    mma_gemm<1><<<dim3(DQ / 128, (B_ * NQ) / 128, 1), 512, GEMM_SMEM>>>(
        aop, nullptr, wop, nullptr, nullptr, nullptr, nullptr, nullptr,
        bo, out);
}

// round 16
// speedup vs baseline: 1.5698x; 1.0331x over previous
#include <cuda_runtime.h>
#include <cuda_fp16.h>
#include <cstdint>

// Problem constants
#define B_     4
#define NQ     2048
#define DQ     1024
#define NK     1024
#define DC     768
#define HEADS  16
#define DH     64
#define INNER  1024   // HEADS*DH

// ---------------------------------------------------------------------------
// Device scratch (static globals). Single fp16 everywhere. Weights natural [K,N].
// ---------------------------------------------------------------------------
__device__ __half g_x [(size_t)B_ * NQ * DQ];
__device__ __half g_c [(size_t)B_ * NK * DC];
__device__ __half g_q [(size_t)B_ * NQ * INNER];
__device__ __half g_k [(size_t)B_ * NK * INNER];
__device__ __half g_v [(size_t)B_ * NK * INNER];
__device__ __half g_ao[(size_t)B_ * NQ * INNER];
__device__ __half g_wq[(size_t)DQ * INNER];
__device__ __half g_wk[(size_t)DC * INNER];
__device__ __half g_wv[(size_t)DC * INNER];
__device__ __half g_wo[(size_t)INNER * DQ];

// ---------------------------------------------------------------------------
// PTX helpers (sm_80-era only: cp.async, ldmatrix, mma.sync)
// ---------------------------------------------------------------------------
__device__ __forceinline__ uint32_t smem_u32(const void* p) {
    uint32_t a;
    asm("{ .reg .u64 t; cvta.to.shared.u64 t, %1; cvt.u32.u64 %0, t; }"
        : "=r"(a) : "l"(p));
    return a;
}
__device__ __forceinline__ void cp_async16(uint32_t s, const void* g) {
    asm volatile("cp.async.cg.shared.global [%0], [%1], 16;" :: "r"(s), "l"(g));
}
__device__ __forceinline__ void ldsm_x4(uint32_t* r, uint32_t a) {
    asm volatile("ldmatrix.sync.aligned.m8n8.x4.shared.b16 {%0,%1,%2,%3}, [%4];"
                 : "=r"(r[0]), "=r"(r[1]), "=r"(r[2]), "=r"(r[3]) : "r"(a));
}
__device__ __forceinline__ void ldsm_x4_t(uint32_t* r, uint32_t a) {
    asm volatile("ldmatrix.sync.aligned.m8n8.x4.trans.shared.b16 {%0,%1,%2,%3}, [%4];"
                 : "=r"(r[0]), "=r"(r[1]), "=r"(r[2]), "=r"(r[3]) : "r"(a));
}
__device__ __forceinline__ void mma_f16(float* d, const uint32_t a[4],
                                        uint32_t b0, uint32_t b1) {
    asm volatile(
        "mma.sync.aligned.m16n8k16.row.col.f32.f16.f16.f32 "
        "{%0,%1,%2,%3}, {%4,%5,%6,%7}, {%8,%9}, {%0,%1,%2,%3};"
        : "+f"(d[0]), "+f"(d[1]), "+f"(d[2]), "+f"(d[3])
        : "r"(a[0]), "r"(a[1]), "r"(a[2]), "r"(a[3]), "r"(b0), "r"(b1));
}
__device__ __forceinline__ uint32_t ex2_h2(uint32_t a) {
    uint32_t r;
    asm("ex2.approx.f16x2 %0, %1;" : "=r"(r) : "r"(a));
    return r;
}
#define SW64(o)  ((o) ^ (((o) >> 3) & 0x30))
#define SW128(o) ((o) ^ (((o) >> 3) & 0x70))
#define CP_COMMIT() asm volatile("cp.async.commit_group;" ::: "memory")
#define CP_WAIT0()  asm volatile("cp.async.wait_group 0;" ::: "memory")
#define CP_WAIT1()  asm volatile("cp.async.wait_group 1;" ::: "memory")

__device__ __forceinline__ uint32_t pack_h(float a, float b) {
    __half2 t = __floats2half2_rn(a, b);
    return *(uint32_t*)&t;
}

// ---------------------------------------------------------------------------
// fp16 GEMM (round-10 exact mainloop): C = A[M,K] @ W[K,N].
// CTA 128x128x32, 512 thr (16 warps 4x4), warp 32x32, 3-stage ring, 48 KB,
// 2 CTAs/SM. MODE 0: fused QKV, z folded into blockIdx.y; MODE 1: f32+bias.
// ---------------------------------------------------------------------------
#define GSTAGE_B  16384                // A(8K) B(8K)
#define GEMM_SMEM (3 * GSTAGE_B)       // 48 KB

template <int MODE>
__global__ __launch_bounds__(512, 2)
void mma_gemm(const __half* __restrict__ Ax, const __half* __restrict__ Ac,
              const __half* __restrict__ W0, const __half* __restrict__ W1,
              const __half* __restrict__ W2,
              __half* __restrict__ C0, __half* __restrict__ C1,
              __half* __restrict__ C2,
              const float* __restrict__ bias, float* __restrict__ Cf)
{
    extern __shared__ __align__(1024) char smraw[];
    const uint32_t sb = smem_u32(smraw);
    const int tid  = threadIdx.x;
    const int wid  = tid >> 5, lane = tid & 31;
    const int wm   = wid & 3,  wn   = wid >> 2;     // 4 x 4 warp grid
    const int lsel = lane & 15;
    const int khf  = (lane >> 4) * 16;
    const int tt   = lane >> 3;

    const __half* A;
    const __half* W;
    __half* Ch;
    int K, yt;
    if (MODE == 1) {
        A = Ax; W = W0; Ch = nullptr; K = INNER; yt = blockIdx.y;
    } else {
        const int yb = blockIdx.y;
        if (yb < 64)      { A = Ax; W = W0; Ch = C0; K = DQ; yt = yb; }
        else if (yb < 96) { A = Ac; W = W1; Ch = C1; K = DC; yt = yb - 64; }
        else              { A = Ac; W = W2; Ch = C2; K = DC; yt = yb - 96; }
    }
    const int row0 = yt * 128, col0 = blockIdx.x * 128;
    const int N = 1024;
    const int nch = K >> 5;

    float acc[2][4][4];
#pragma unroll
    for (int i = 0; i < 2; i++)
#pragma unroll
        for (int j = 0; j < 4; j++)
#pragma unroll
            for (int q = 0; q < 4; q++) acc[i][j][q] = 0.f;

    const __half* aT = A + (size_t)row0 * K;

#define GISSUE(c)                                                              \
    do {                                                                       \
        const uint32_t stg_ = sb + ((c) % 3) * GSTAGE_B;                       \
        const int k0_ = (c) << 5;                                              \
        {                                                                      \
            const int cc = tid;                                                \
            const int r = cc >> 2, cl = cc & 3;                                \
            const uint32_t off = r * 64 + cl * 16;                             \
            cp_async16(stg_ + SW64(off), aT + (size_t)r * K + k0_ + cl * 8);   \
        }                                                                      \
        {                                                                      \
            const int cc = tid;                                                \
            const int half = cc >> 8;                                          \
            const int c2 = cc & 255;                                           \
            const int r = c2 >> 3, seg = c2 & 7;                               \
            const uint32_t off = r * 128 + seg * 16;                           \
            cp_async16(stg_ + 8192 + half * 4096 + SW128(off),                 \
                       W + (size_t)(k0_ + r) * N + col0 + half * 64 + seg * 8);\
        }                                                                      \
        CP_COMMIT();                                                           \
    } while (0)

    GISSUE(0);
    GISSUE(1);
    for (int c = 0; c < nch; c++) {
        if (c + 1 < nch) { CP_WAIT1(); } else { CP_WAIT0(); }
        __syncthreads();
        if (c + 2 < nch) GISSUE(c + 2);

        const uint32_t stg = sb + (c % 3) * GSTAGE_B;
#pragma unroll
        for (int ks = 0; ks < 2; ks++) {
            uint32_t af[2][4], bf[2][4];
#pragma unroll
            for (int mt = 0; mt < 2; mt++) {
                const uint32_t off = (wm * 32 + mt * 16 + lsel) * 64 + ks * 32 + khf;
                ldsm_x4(af[mt], stg + SW64(off));
            }
#pragma unroll
            for (int gg = 0; gg < 2; gg++) {
                const int g = (wn & 1) * 2 + gg;
                const uint32_t off = (ks * 16 + (lane & 7) + ((tt >> 1) << 3)) * 128
                                     + g * 32 + (tt & 1) * 16;
                const uint32_t sw = SW128(off) + (wn >> 1) * 4096;
                ldsm_x4_t(bf[gg], stg + 8192 + sw);
            }
#pragma unroll
            for (int gg = 0; gg < 2; gg++)
#pragma unroll
                for (int mt = 0; mt < 2; mt++)
#pragma unroll
                    for (int nt = 0; nt < 2; nt++)
                        mma_f16(acc[mt][gg * 2 + nt], af[mt], bf[gg][nt], bf[gg][2 + nt]);
        }
    }
#undef GISSUE

    const int rb = row0 + wm * 32 + (lane >> 2);
    const int cb = col0 + wn * 32 + (lane & 3) * 2;
#pragma unroll
    for (int mt = 0; mt < 2; mt++) {
#pragma unroll
        for (int j = 0; j < 4; j++) {
            const int col = cb + j * 8;
            const int r0 = rb + mt * 16;
            float d0 = acc[mt][j][0], d1 = acc[mt][j][1];
            float d2 = acc[mt][j][2], d3 = acc[mt][j][3];
            if (MODE == 1) {
                float b0 = bias[col], b1 = bias[col + 1];
                *(float2*)(Cf + (size_t)r0 * N + col)       = make_float2(d0 + b0, d1 + b1);
                *(float2*)(Cf + (size_t)(r0 + 8) * N + col) = make_float2(d2 + b0, d3 + b1);
            } else {
                *(uint32_t*)(Ch + (size_t)r0 * N + col)       = pack_h(d0, d1);
                *(uint32_t*)(Ch + (size_t)(r0 + 8) * N + col) = pack_h(d2, d3);
            }
        }
    }
}

// ---------------------------------------------------------------------------
// Flash attention via fp16 mma.sync single-pass (2-stage KV ring, 48 KB).
// NEW: log2-domain softmax with ex2.approx.f16x2 (half the MUFU ops, no
// FMULs, P born fp16) and row-sum l via ones-MMA on the tensor pipe.
// ---------------------------------------------------------------------------
#define AQ_OFF   0
#define AR_BASE  16384
#define AR_STAGE 16384
#define AV_OFF   8192
#define ATTN_SMEM (16384 + 2 * 16384)   // 48 KB

__global__ __launch_bounds__(256, 2)
void attn_mma(const __half* __restrict__ qg, const __half* __restrict__ kg,
              const __half* __restrict__ vg, __half* __restrict__ aog)
{
    extern __shared__ __align__(1024) char smraw[];
    const uint32_t sb = smem_u32(smraw);
    const int tid = threadIdx.x, lane = tid & 31, w = tid >> 5;
    const int q0 = blockIdx.x * 128;
    const int h  = blockIdx.y;
    const int b  = blockIdx.z;
    const int lsel = lane & 15;
    const int khf  = (lane >> 4) * 16;
    const float SC2 = 0.18033688011112042f;  // 0.125 * log2(e)
    const uint32_t ONES = 0x3C003C00u;       // half2(1.0, 1.0)

    // Load Q tile [128 x 64] fp16 into smem (row 128B, SW128)
    const size_t qgb = ((size_t)b * NQ + q0) * INNER + h * DH;
#pragma unroll
    for (int j = 0; j < 4; j++) {
        int idx = tid + 256 * j;           // 0..1023
        int r = idx >> 3, seg = idx & 7;
        uint32_t off = r * 128 + seg * 16;
        *(float4*)(smraw + AQ_OFF + SW128(off)) =
            *(const float4*)(qg + qgb + (size_t)r * INNER + seg * 8);
    }

    float oacc[8][4];
#pragma unroll
    for (int j = 0; j < 8; j++)
#pragma unroll
        for (int q = 0; q < 4; q++) oacc[j][q] = 0.f;
    float m0 = -1e30f, m1 = -1e30f, l0 = 0.f, l1 = 0.f;

#define AT_ISSUE(kt)                                                           \
    do {                                                                       \
        const uint32_t stg_ = sb + AR_BASE + ((kt) & 1) * AR_STAGE;            \
        const size_t kvg = ((size_t)b * NK + (kt) * 64) * INNER + h * DH;      \
        _Pragma("unroll")                                                      \
        for (int j = 0; j < 4; j++) {                                          \
            int idx = tid + 256 * j;       /* 0..1023 */                       \
            int buf = idx >> 9;            /* 0:K 1:V */                       \
            int cc  = idx & 511;                                               \
            int r = cc >> 3, seg = cc & 7;                                     \
            uint32_t off = r * 128 + seg * 16;                                 \
            const __half* src = (buf ? vg : kg) + kvg + (size_t)r * INNER + seg * 8; \
            cp_async16(stg_ + buf * 8192 + SW128(off), src);                   \
        }                                                                      \
        CP_COMMIT();                                                           \
    } while (0)

    const int NT = NK / 64;
    AT_ISSUE(0);
    for (int kt = 0; kt < NT; kt++) {
        CP_WAIT0();
        __syncthreads();                 // tile kt visible; prev compute done
        if (kt + 1 < NT) AT_ISSUE(kt + 1);
        const uint32_t stg = sb + AR_BASE + (kt & 1) * AR_STAGE;

        // ---- S = Q @ K^T ----
        float sacc[8][4];
#pragma unroll
        for (int j = 0; j < 8; j++)
#pragma unroll
            for (int q = 0; q < 4; q++) sacc[j][q] = 0.f;

#pragma unroll
        for (int ks = 0; ks < 4; ks++) {
            uint32_t qf[4];
            {
                uint32_t off = (w * 16 + lsel) * 128 + ks * 32 + khf;
                ldsm_x4(qf, sb + AQ_OFF + SW128(off));
            }
#pragma unroll
            for (int g = 0; g < 4; g++) {
                uint32_t kf[4];
                uint32_t off = (g * 16 + lsel) * 128 + ks * 32 + khf;
                ldsm_x4(kf, stg + SW128(off));
#pragma unroll
                for (int nt = 0; nt < 2; nt++)
                    mma_f16(sacc[g * 2 + nt], qf, kf[nt], kf[2 + nt]);
            }
        }

        // ---- online softmax (log2 domain) ----
        float rx0 = -1e30f, rx1 = -1e30f;
#pragma unroll
        for (int j = 0; j < 8; j++) {
            rx0 = fmaxf(rx0, fmaxf(sacc[j][0], sacc[j][1]));
            rx1 = fmaxf(rx1, fmaxf(sacc[j][2], sacc[j][3]));
        }
#pragma unroll
        for (int off = 1; off <= 2; off <<= 1) {
            rx0 = fmaxf(rx0, __shfl_xor_sync(0xffffffffu, rx0, off));
            rx1 = fmaxf(rx1, __shfl_xor_sync(0xffffffffu, rx1, off));
        }
        float nm0 = fmaxf(m0, rx0 * SC2), nm1 = fmaxf(m1, rx1 * SC2);
        float c0 = exp2f(m0 - nm0), c1 = exp2f(m1 - nm1);
        m0 = nm0; m1 = nm1;

        // P = exp2(S*SC2 - m) computed directly in fp16 pairs
        uint32_t pa[4][4];
#pragma unroll
        for (int t = 0; t < 4; t++) {
#pragma unroll
            for (int jj = 0; jj < 2; jj++) {
                int j = 2 * t + jj;
                float a00 = fmaf(sacc[j][0], SC2, -nm0);
                float a01 = fmaf(sacc[j][1], SC2, -nm0);
                float a10 = fmaf(sacc[j][2], SC2, -nm1);
                float a11 = fmaf(sacc[j][3], SC2, -nm1);
                pa[t][jj * 2]     = ex2_h2(pack_h(a00, a01));
                pa[t][jj * 2 + 1] = ex2_h2(pack_h(a10, a11));
            }
        }

        // row sums via ones-MMA (consistent with fp16 P used in numerator)
        float lacc[4] = {0.f, 0.f, 0.f, 0.f};
#pragma unroll
        for (int t = 0; t < 4; t++)
            mma_f16(lacc, pa[t], ONES, ONES);
        l0 = l0 * c0 + lacc[0];
        l1 = l1 * c1 + lacc[2];
#pragma unroll
        for (int j = 0; j < 8; j++) {
            oacc[j][0] *= c0; oacc[j][1] *= c0;
            oacc[j][2] *= c1; oacc[j][3] *= c1;
        }

        // ---- O += P @ V ----
        const int tt = lane >> 3;
#pragma unroll
        for (int t = 0; t < 4; t++) {
#pragma unroll
            for (int g = 0; g < 4; g++) {
                uint32_t vf[4];
                uint32_t off = (t * 16 + (lane & 7) + (tt >> 1) * 8) * 128
                               + g * 32 + (tt & 1) * 16;
                ldsm_x4_t(vf, stg + AV_OFF + SW128(off));
#pragma unroll
                for (int nt = 0; nt < 2; nt++)
                    mma_f16(oacc[g * 2 + nt], pa[t], vf[nt], vf[2 + nt]);
            }
        }
    }
#undef AT_ISSUE

    const float inv0 = 1.f / l0, inv1 = 1.f / l1;
    const int r0g = q0 + w * 16 + (lane >> 2);
    const int r1g = r0g + 8;
    const int cbase = h * DH + (lane & 3) * 2;
#pragma unroll
    for (int j = 0; j < 8; j++) {
        const int col = cbase + j * 8;
        *(uint32_t*)(aog + ((size_t)b * NQ + r0g) * INNER + col) =
            pack_h(oacc[j][0] * inv0, oacc[j][1] * inv0);
        *(uint32_t*)(aog + ((size_t)b * NQ + r1g) * INNER + col) =
            pack_h(oacc[j][2] * inv1, oacc[j][3] * inv1);
    }
}

// ---------------------------------------------------------------------------
// fp32 -> fp16 converts, split in two launches (attn at ncu slot 3)
// ---------------------------------------------------------------------------
#define N4_X  (B_ * NQ * DQ / 4)
#define N4_C  (B_ * NK * DC / 4)
#define ACT_TOT (N4_X + N4_C)
#define N4_WQ (DQ * INNER / 4)
#define N4_WK (DC * INNER / 4)
#define N4_WV (DC * INNER / 4)
#define N4_WO (INNER * DQ / 4)
#define W1_ (N4_WQ)
#define W2_ (W1_ + N4_WK)
#define W3_ (W2_ + N4_WV)
#define W4_ (W3_ + N4_WO)

__global__ void cvt_act(const float4* __restrict__ x, const float4* __restrict__ ctx)
{
    int i = blockIdx.x * blockDim.x + threadIdx.x;
    if (i >= ACT_TOT) return;
    const float4* in;
    __half2* dst;
    int idx;
    if (i < N4_X) { in = x;   dst = (__half2*)g_x; idx = i; }
    else          { in = ctx; dst = (__half2*)g_c; idx = i - N4_X; }
    float4 v = in[idx];
    dst[2 * idx]     = __floats2half2_rn(v.x, v.y);
    dst[2 * idx + 1] = __floats2half2_rn(v.z, v.w);
}

__global__ void cvt_w(const float4* __restrict__ wq, const float4* __restrict__ wk,
                      const float4* __restrict__ wv, const float4* __restrict__ wo)
{
    int i = blockIdx.x * blockDim.x + threadIdx.x;
    if (i >= W4_) return;
    const float4* in;
    __half2* dst;
    int idx;
    if      (i < W1_) { in = wq; dst = (__half2*)g_wq; idx = i; }
    else if (i < W2_) { in = wk; dst = (__half2*)g_wk; idx = i - W1_; }
    else if (i < W3_) { in = wv; dst = (__half2*)g_wv; idx = i - W2_; }
    else              { in = wo; dst = (__half2*)g_wo; idx = i - W3_; }
    float4 v = in[idx];
    dst[2 * idx]     = __floats2half2_rn(v.x, v.y);
    dst[2 * idx + 1] = __floats2half2_rn(v.z, v.w);
}

// ---------------------------------------------------------------------------
// Launch: cvt_act(0), cvt_w(1), gemmQKV(2), attn(3) <- ncu slot, gemmO(4)
// ---------------------------------------------------------------------------
extern "C" void kernel_launch(void* const* d_in, const int* in_sizes, int n_in,
                              void* d_out, int out_size)
{
    const float* x   = (const float*)d_in[0];
    const float* ctx = (const float*)d_in[1];
    const float* Wq  = (const float*)d_in[2];
    const float* Wk  = (const float*)d_in[3];
    const float* Wv  = (const float*)d_in[4];
    const float* Wo  = (const float*)d_in[5];
    const float* bo  = (const float*)d_in[6];
    float* out = (float*)d_out;

    __half *xp, *cp, *qp, *kp, *vp, *aop, *wqp, *wkp, *wvp, *wop;
    cudaGetSymbolAddress((void**)&xp,  g_x);
    cudaGetSymbolAddress((void**)&cp,  g_c);
    cudaGetSymbolAddress((void**)&qp,  g_q);
    cudaGetSymbolAddress((void**)&kp,  g_k);
    cudaGetSymbolAddress((void**)&vp,  g_v);
    cudaGetSymbolAddress((void**)&aop, g_ao);
    cudaGetSymbolAddress((void**)&wqp, g_wq);
    cudaGetSymbolAddress((void**)&wkp, g_wk);
    cudaGetSymbolAddress((void**)&wvp, g_wv);
    cudaGetSymbolAddress((void**)&wop, g_wo);

    cudaFuncSetAttribute(mma_gemm<0>, cudaFuncAttributeMaxDynamicSharedMemorySize, GEMM_SMEM);
    cudaFuncSetAttribute(mma_gemm<1>, cudaFuncAttributeMaxDynamicSharedMemorySize, GEMM_SMEM);
    cudaFuncSetAttribute(attn_mma, cudaFuncAttributeMaxDynamicSharedMemorySize, ATTN_SMEM);

    // 0: convert activations
    cvt_act<<<(ACT_TOT + 255) / 256, 256>>>((const float4*)x, (const float4*)ctx);
    // 1: convert weights
    cvt_w<<<(W4_ + 255) / 256, 256>>>((const float4*)Wq, (const float4*)Wk,
                                      (const float4*)Wv, (const float4*)Wo);

    // 2: fused Q+K+V projections, compact grid (y: [0,64)=Q, [64,96)=K, [96,128)=V)
    mma_gemm<0><<<dim3(INNER / 128, 128, 1), 512, GEMM_SMEM>>>(
        xp, cp, wqp, wkp, wvp, qp, kp, vp, nullptr, nullptr);

    // 3: attention (ncu capture slot)
    attn_mma<<<dim3(NQ / 128, HEADS, B_), 256, ATTN_SMEM>>>(qp, kp, vp, aop);

    // 4: output projection -> fp32 + bias
    mma_gemm<1><<<dim3(DQ / 128, (B_ * NQ) / 128, 1), 512, GEMM_SMEM>>>(
        aop, nullptr, wop, nullptr, nullptr, nullptr, nullptr, nullptr,
        bo, out);
}